// round 15
// baseline (speedup 1.0000x reference)
#include <cuda_runtime.h>
#include <cuda_bf16.h>

#define NL 1000
#define ND 512
#define NH 8
#define NDK 64
#define NRR 1999
#define NBH 64
#define LOG2E 1.4426950408889634f

// ---------------- device scratch: pre-permuted bf16 fragment arrays -----------
__device__ unsigned g_xnp [500 * 32 * 128];   // xn  A-perm (8000 x 512)
__device__ unsigned g_ctxp[500 * 32 * 128];   // ctx A-perm (8000 x 512)
__device__ unsigned g_wp  [4 * 131072];       // W   B-perm (512k x 512n) x4
__device__ unsigned g_qp  [NBH * 32768];      // q per bh: A-perm (1024 x 64)
__device__ unsigned g_kp  [NBH * 32768];      // k per bh: pair-packed B (k=d, n=j)
__device__ unsigned g_vp  [NBH * 32768];      // v per bh: pair-packed B (k=j, n=d)
__device__ unsigned g_relp[4 * 136 * 128];    // rel*log2e pair-packed B (k=d, n=u+72)

// ---------------- helpers -----------------------------------------------------
__device__ __forceinline__ unsigned bf2(float lo, float hi) {
    unsigned r;
    asm("cvt.rn.bf16x2.f32 %0, %1, %2;" : "=r"(r) : "f"(hi), "f"(lo));
    return r;
}
__device__ __forceinline__ float ex2f(float x) {
    float r;
    asm("ex2.approx.ftz.f32 %0, %1;" : "=f"(r) : "f"(x));
    return r;
}
__device__ __forceinline__ void mma16(float4& d, uint4 a, uint2 b) {
    asm volatile(
        "mma.sync.aligned.m16n8k16.row.col.f32.bf16.bf16.f32 "
        "{%0,%1,%2,%3}, {%4,%5,%6,%7}, {%8,%9}, {%0,%1,%2,%3};\n"
        : "+f"(d.x), "+f"(d.y), "+f"(d.z), "+f"(d.w)
        : "r"(a.x), "r"(a.y), "r"(a.z), "r"(a.w), "r"(b.x), "r"(b.y));
}
// A tile 16x16 (u32 = bf16x2 over k)
__device__ __forceinline__ int a_off16(int m, int k, int nkt16) {
    return (((m >> 4) * nkt16 + (k >> 4)) << 7) +
           ((((m & 7) << 2) + ((k & 7) >> 1)) << 2) + ((m >> 3) & 1) + (((k >> 3) & 1) << 1);
}
// classic B tile 16x8 (for g_wp only)
__device__ __forceinline__ int b_off16(int k, int n, int nnt) {
    return (((k >> 4) * nnt + (n >> 3)) << 6) +
           ((((n & 7) << 2) + ((k & 7) >> 1)) << 1) + ((k >> 3) & 1);
}
// pair-packed B: two n8 tiles per 128-word block, per-lane 4 words
__device__ __forceinline__ int bp_off(int k, int n, int NP) {
    return (((k >> 4) * NP + (n >> 4)) << 7) +
           ((((n & 7) << 2) + ((k & 7) >> 1)) << 2) + (((n >> 3) & 1) << 1) + ((k >> 3) & 1);
}

// ---------------- fused preamble (lean): wconv + relconv + zfill + warp-LN ----
// blocks: [0,512) wconv 4w/thr | [512,580) relconv 4w/thr | [580,644) zfill
//         [644,1644) layernorm: warp per row
__global__ void prep_kernel(const float* __restrict__ W0, const float* __restrict__ W1,
                            const float* __restrict__ W2, const float* __restrict__ W3,
                            const float* __restrict__ rel,
                            const float* __restrict__ x,
                            const float* __restrict__ gamma,
                            const float* __restrict__ beta) {
    int bid = blockIdx.x;
    if (bid < 512) {
        int gt = (bid << 8) + threadIdx.x;            // 131072 threads
        int widx = gt >> 15;
        const float* W = (widx == 0) ? W0 : (widx == 1) ? W1 : (widx == 2) ? W2 : W3;
        int t = gt & 32767;
        int n = t >> 6, k0 = (t & 63) << 3;
        float4 va = *(const float4*)&W[(size_t)n * ND + k0];
        float4 vb = *(const float4*)&W[(size_t)n * ND + k0 + 4];
        unsigned* wp = g_wp + widx * 131072;
        wp[b_off16(k0 + 0, n, 64)] = bf2(va.x, va.y);
        wp[b_off16(k0 + 2, n, 64)] = bf2(va.z, va.w);
        wp[b_off16(k0 + 4, n, 64)] = bf2(vb.x, vb.y);
        wp[b_off16(k0 + 6, n, 64)] = bf2(vb.z, vb.w);
    } else if (bid < 580) {
        int t = ((bid - 512) << 8) + threadIdx.x;     // 17408 threads
        int u = t >> 3, k0 = (t & 7) << 3;
        int ua = u - 72;
        float4 va = make_float4(0.f, 0.f, 0.f, 0.f);
        float4 vb = make_float4(0.f, 0.f, 0.f, 0.f);
        if (ua >= 0 && ua < NRR) {
            va = *(const float4*)&rel[(size_t)ua * NDK + k0];
            vb = *(const float4*)&rel[(size_t)ua * NDK + k0 + 4];
        }
        g_relp[bp_off(k0 + 0, u, 136)] = bf2(va.x * LOG2E, va.y * LOG2E);
        g_relp[bp_off(k0 + 2, u, 136)] = bf2(va.z * LOG2E, va.w * LOG2E);
        g_relp[bp_off(k0 + 4, u, 136)] = bf2(vb.x * LOG2E, vb.y * LOG2E);
        g_relp[bp_off(k0 + 6, u, 136)] = bf2(vb.z * LOG2E, vb.w * LOG2E);
    } else if (bid < 644) {
        int bh = bid - 580;
        for (int f = threadIdx.x; f < 768; f += 256) {
            int m = 1000 + (f >> 5);
            int k = (f & 31) << 1;
            g_qp[bh * 32768 + a_off16(m, k, 4)] = 0;
            g_kp[bh * 32768 + bp_off(k, m, 64)] = 0;
            int k0v = 1000 + ((f >> 6) << 1);
            int dv = f & 63;
            g_vp[bh * 32768 + bp_off(k0v, dv, 4)] = 0;
        }
    } else {
        // layernorm: warp per row, 8 rows per 256-thread block
        int lane = threadIdx.x & 31, wp = threadIdx.x >> 5;
        int row = ((bid - 644) << 3) + wp;
        const float4* xr = (const float4*)(x + (size_t)row * ND);
        float4 v[4];
#pragma unroll
        for (int i = 0; i < 4; i++) v[i] = xr[lane + (i << 5)];
        float s = 0.f;
#pragma unroll
        for (int i = 0; i < 4; i++) s += v[i].x + v[i].y + v[i].z + v[i].w;
#pragma unroll
        for (int o = 16; o; o >>= 1) s += __shfl_xor_sync(0xffffffffu, s, o);
        float mean = s * (1.0f / ND);
        float s2 = 0.f;
#pragma unroll
        for (int i = 0; i < 4; i++) {
            float a = v[i].x - mean, b = v[i].y - mean;
            float c = v[i].z - mean, d = v[i].w - mean;
            s2 += a * a + b * b + c * c + d * d;
        }
#pragma unroll
        for (int o = 16; o; o >>= 1) s2 += __shfl_xor_sync(0xffffffffu, s2, o);
        float inv = rsqrtf(s2 * (1.0f / ND) + 1e-5f);
#pragma unroll
        for (int i = 0; i < 4; i++) {
            float4 gg = ((const float4*)gamma)[lane + (i << 5)];
            float4 bt = ((const float4*)beta)[lane + (i << 5)];
            int k0 = (lane + (i << 5)) << 2;
            float o0 = (v[i].x - mean) * inv * gg.x + bt.x;
            float o1 = (v[i].y - mean) * inv * gg.y + bt.y;
            float o2 = (v[i].z - mean) * inv * gg.z + bt.z;
            float o3 = (v[i].w - mean) * inv * gg.w + bt.w;
            g_xnp[a_off16(row, k0, 32)] = bf2(o0, o1);
            g_xnp[a_off16(row, k0 + 2, 32)] = bf2(o2, o3);
        }
    }
}

// ---------------- streaming bf16 GEMM: depth-3 register pipeline --------------
__global__ void __launch_bounds__(128) gemm2_kernel(
    const float* __restrict__ b0, const float* __restrict__ b1,
    const float* __restrict__ b2, const float* __restrict__ resid,
    float* __restrict__ Cf, int outproj) {
    const int tid = threadIdx.x, lane = tid & 31, warp = tid >> 5;
    const int wm = warp >> 1, wn = warp & 1, g = lane >> 2, tig = lane & 3;
    const int m0 = blockIdx.y * 64, n0 = blockIdx.x * 64;
    const int z = blockIdx.z;
    const int mode = outproj ? 1 : (z == 0 ? 0 : (z == 1 ? 2 : 3));
    const int widx = outproj ? 3 : z;
    const float* bias = outproj ? b0 : (z == 0 ? b0 : (z == 1 ? b1 : b2));
    const unsigned* Ap = outproj ? g_ctxp : g_xnp;
    const unsigned* Ab = Ap + (size_t)(((m0 + wm * 32) >> 4) * 32) * 128 + (lane << 2);
    const unsigned* Bb = g_wp + (size_t)widx * 131072 + (size_t)((n0 >> 3) + wn * 4) * 64 + (lane << 1);

    float4 acc[2][4] = {};
    uint4 a[3][2];
    uint2 b[3][4];
#pragma unroll
    for (int s = 0; s < 2; s++) {
        a[s][0] = *(const uint4*)(Ab + s * 128);
        a[s][1] = *(const uint4*)(Ab + 4096 + s * 128);
#pragma unroll
        for (int j = 0; j < 4; j++)
            b[s][j] = *(const uint2*)(Bb + (size_t)s * 4096 + j * 64);
    }
#pragma unroll
    for (int kt = 0; kt < 32; kt++) {
        int cur = kt % 3, nxt = (kt + 2) % 3;
        if (kt < 30) {
            a[nxt][0] = *(const uint4*)(Ab + (kt + 2) * 128);
            a[nxt][1] = *(const uint4*)(Ab + 4096 + (kt + 2) * 128);
#pragma unroll
            for (int j = 0; j < 4; j++)
                b[nxt][j] = *(const uint2*)(Bb + (size_t)(kt + 2) * 4096 + j * 64);
        }
#pragma unroll
        for (int j = 0; j < 4; j++) {
            mma16(acc[0][j], a[cur][0], b[cur][j]);
            mma16(acc[1][j], a[cur][1], b[cur][j]);
        }
    }

    const float KS = 0.125f * LOG2E;
#pragma unroll
    for (int i = 0; i < 2; i++)
#pragma unroll
        for (int j = 0; j < 4; j++) {
            int col = n0 + wn * 32 + j * 8 + (tig << 1);
            float2 bb = *(const float2*)&bias[col];
            float4 c = acc[i][j];
            float cx = c.x + bb.x, cy = c.y + bb.y;
            float cz = c.z + bb.x, cw = c.w + bb.y;
            int r0 = m0 + wm * 32 + i * 16 + g, r1 = r0 + 8;
            if (mode == 1) {
                size_t o0 = (size_t)r0 * ND + col, o1 = (size_t)r1 * ND + col;
                float2 rr0 = *(const float2*)&resid[o0];
                float2 rr1 = *(const float2*)&resid[o1];
                *(float2*)&Cf[o0] = make_float2(cx + rr0.x, cy + rr0.y);
                *(float2*)&Cf[o1] = make_float2(cz + rr1.x, cw + rr1.y);
            } else if (mode == 3) {
                float ox = __shfl_xor_sync(0xffffffffu, cx, 4);
                float oy = __shfl_xor_sync(0xffffffffu, cy, 4);
                float oz = __shfl_xor_sync(0xffffffffu, cz, 4);
                float ow = __shfl_xor_sync(0xffffffffu, cw, 4);
                if (!(g & 1)) {
                    int h = col >> 6, d = col & 63;
                    int b0i = r0 / NL, l0 = r0 - b0i * NL;
                    int b1i = r1 / NL, l1 = r1 - b1i * NL;
                    unsigned* vp0 = g_vp + (b0i * NH + h) * 32768;
                    unsigned* vp1 = g_vp + (b1i * NH + h) * 32768;
                    vp0[bp_off(l0, d, 4)] = bf2(cx, ox);
                    vp0[bp_off(l0, d + 1, 4)] = bf2(cy, oy);
                    vp1[bp_off(l1, d, 4)] = bf2(cz, oz);
                    vp1[bp_off(l1, d + 1, 4)] = bf2(cw, ow);
                }
            } else {
                int h = col >> 6, d = col & 63;
                int b0i = r0 / NL, l0 = r0 - b0i * NL;
                int b1i = r1 / NL, l1 = r1 - b1i * NL;
                int bh0 = b0i * NH + h, bh1 = b1i * NH + h;
                if (mode == 0) {
                    g_qp[bh0 * 32768 + a_off16(l0, d, 4)] = bf2(cx, cy);
                    g_qp[bh1 * 32768 + a_off16(l1, d, 4)] = bf2(cz, cw);
                } else {
                    g_kp[bh0 * 32768 + bp_off(d, l0, 64)] = bf2(cx * KS, cy * KS);
                    g_kp[bh1 * 32768 + bp_off(d, l1, 64)] = bf2(cz * KS, cw * KS);
                }
            }
        }
}

// ---------------- flash attention: warp-exclusive rows, pair-packed loads -----
#define S2STRIDE 19

__global__ void __launch_bounds__(128) attn_kernel() {
    __shared__ float S2all[4 * 128 * S2STRIDE];

    const int it = blockIdx.x, bh = blockIdx.y;
    const int bq = bh >> 3, h = bh & 7;
    const int i0 = it << 6;
    const int tid = threadIdx.x;
    const int lane = tid & 31, w = tid >> 5;
    const int g = lane >> 2, tig = lane & 3;
    float* S2w = S2all + w * 128 * S2STRIDE;

    const unsigned* qpb = g_qp + bh * 32768;
    const unsigned* kpb = g_kp + bh * 32768;
    const unsigned* vpb = g_vp + bh * 32768;

    uint4 qf[4];
#pragma unroll
    for (int kt = 0; kt < 4; kt++)
        qf[kt] = *(const uint4*)(qpb + (size_t)(((it << 2) + w) * 4 + kt) * 128 + (lane << 2));

    float rm0 = -1e30f, rm1 = -1e30f, rl0 = 0.f, rl1 = 0.f;
    float4 O[8] = {};

    const int nboff = (1056 - i0 - (w << 4)) >> 3;

    // warm the ring: v in [0, 80) -> 5 tile-pairs
#pragma unroll
    for (int p = 0; p < 5; p++) {
        int pair = p + (nboff >> 1);
        float4 a0 = make_float4(0.f, 0.f, 0.f, 0.f);
        float4 a1 = make_float4(0.f, 0.f, 0.f, 0.f);
#pragma unroll
        for (int kt = 0; kt < 4; kt++) {
            uint4 bb = *(const uint4*)(g_relp + (((size_t)kt * 136 + pair) << 7) + (lane << 2));
            mma16(a0, qf[kt], make_uint2(bb.x, bb.y));
            mma16(a1, qf[kt], make_uint2(bb.z, bb.w));
        }
        int sl = (p << 4) + (tig << 1);
        S2w[sl * S2STRIDE + g] = a0.x;
        S2w[(sl + 1) * S2STRIDE + g] = a0.y;
        S2w[sl * S2STRIDE + g + 8] = a0.z;
        S2w[(sl + 1) * S2STRIDE + g + 8] = a0.w;
        S2w[(sl + 8) * S2STRIDE + g] = a1.x;
        S2w[(sl + 9) * S2STRIDE + g] = a1.y;
        S2w[(sl + 8) * S2STRIDE + g + 8] = a1.z;
        S2w[(sl + 9) * S2STRIDE + g + 8] = a1.w;
    }
    __syncwarp();

    for (int jt = 0; jt < 16; jt++) {
        const int j0 = jt << 6;

        // S2: new band tiles v in [j0+16, j0+80) -> 4 tile-pairs into ring
#pragma unroll
        for (int p = 0; p < 4; p++) {
            int v8 = ((j0 + 16) >> 3) + (p << 1);
            int pair = (v8 + nboff) >> 1;
            float4 a0 = make_float4(0.f, 0.f, 0.f, 0.f);
            float4 a1 = make_float4(0.f, 0.f, 0.f, 0.f);
#pragma unroll
            for (int kt = 0; kt < 4; kt++) {
                uint4 bb = *(const uint4*)(g_relp + (((size_t)kt * 136 + pair) << 7) + (lane << 2));
                mma16(a0, qf[kt], make_uint2(bb.x, bb.y));
                mma16(a1, qf[kt], make_uint2(bb.z, bb.w));
            }
            int sl = ((j0 + 16 + (p << 4)) & 127) + (tig << 1);
            S2w[sl * S2STRIDE + g] = a0.x;
            S2w[(sl + 1) * S2STRIDE + g] = a0.y;
            S2w[sl * S2STRIDE + g + 8] = a0.z;
            S2w[(sl + 1) * S2STRIDE + g + 8] = a0.w;
            S2w[(sl + 8) * S2STRIDE + g] = a1.x;
            S2w[(sl + 9) * S2STRIDE + g] = a1.y;
            S2w[(sl + 8) * S2STRIDE + g + 8] = a1.z;
            S2w[(sl + 9) * S2STRIDE + g + 8] = a1.w;
        }
        __syncwarp();

        // S1 = Q @ K^T over 4 n8-tile pairs
        float4 s1[8] = {};
#pragma unroll
        for (int kt = 0; kt < 4; kt++) {
#pragma unroll
            for (int p = 0; p < 4; p++) {
                uint4 kk = *(const uint4*)(kpb +
                    (((size_t)(kt * 64 + (j0 >> 4) + p)) << 7) + (lane << 2));
                mma16(s1[2 * p], qf[kt], make_uint2(kk.x, kk.y));
                mma16(s1[2 * p + 1], qf[kt], make_uint2(kk.z, kk.w));
            }
        }

        // gather ring + mask + row max (warp-local)
        float m0 = -1e30f, m1 = -1e30f;
#pragma unroll
        for (int nt = 0; nt < 8; nt++) {
            int c = (nt << 3) + (tig << 1);
            int v0 = j0 + c - g + 15;
            int v1 = v0 - 8;
            s1[nt].x += S2w[(v0 & 127) * S2STRIDE + g];
            s1[nt].y += S2w[((v0 + 1) & 127) * S2STRIDE + g];
            s1[nt].z += S2w[(v1 & 127) * S2STRIDE + g + 8];
            s1[nt].w += S2w[((v1 + 1) & 127) * S2STRIDE + g + 8];
            if (j0 + c >= NL) { s1[nt].x = -1e30f; s1[nt].z = -1e30f; }
            if (j0 + c + 1 >= NL) { s1[nt].y = -1e30f; s1[nt].w = -1e30f; }
            m0 = fmaxf(m0, fmaxf(s1[nt].x, s1[nt].y));
            m1 = fmaxf(m1, fmaxf(s1[nt].z, s1[nt].w));
        }
        m0 = fmaxf(m0, __shfl_xor_sync(0xffffffffu, m0, 1));
        m0 = fmaxf(m0, __shfl_xor_sync(0xffffffffu, m0, 2));
        m1 = fmaxf(m1, __shfl_xor_sync(0xffffffffu, m1, 1));
        m1 = fmaxf(m1, __shfl_xor_sync(0xffffffffu, m1, 2));

        // prefetch kt=0 V fragments — latency hides under the exp2/shfl work below
        uint4 vv0[4];
#pragma unroll
        for (int p = 0; p < 4; p++)
            vv0[p] = *(const uint4*)(vpb + (((size_t)((j0 >> 4) << 2)) << 7) +
                                     (p << 7) + (lane << 2));

        float mn0 = fmaxf(rm0, m0), mn1 = fmaxf(rm1, m1);
        float a0 = ex2f(rm0 - mn0), a1 = ex2f(rm1 - mn1);
        rm0 = mn0; rm1 = mn1;

        unsigned plo[8], phi[8];
        float s0 = 0.f, sh = 0.f;
#pragma unroll
        for (int nt = 0; nt < 8; nt++) {
            float e00 = ex2f(s1[nt].x - mn0), e01 = ex2f(s1[nt].y - mn0);
            float e10 = ex2f(s1[nt].z - mn1), e11 = ex2f(s1[nt].w - mn1);
            plo[nt] = bf2(e00, e01);
            phi[nt] = bf2(e10, e11);
            s0 += e00 + e01;
            sh += e10 + e11;
        }
        s0 += __shfl_xor_sync(0xffffffffu, s0, 1);
        s0 += __shfl_xor_sync(0xffffffffu, s0, 2);
        sh += __shfl_xor_sync(0xffffffffu, sh, 1);
        sh += __shfl_xor_sync(0xffffffffu, sh, 2);
        rl0 = rl0 * a0 + s0;
        rl1 = rl1 * a1 + sh;

        // O rescale, then O += P @ V
#pragma unroll
        for (int dnt = 0; dnt < 8; dnt++) {
            O[dnt].x *= a0; O[dnt].y *= a0;
            O[dnt].z *= a1; O[dnt].w *= a1;
        }
        {
            uint4 pa = make_uint4(plo[0], phi[0], plo[1], phi[1]);
#pragma unroll
            for (int p = 0; p < 4; p++) {
                mma16(O[2 * p], pa, make_uint2(vv0[p].x, vv0[p].y));
                mma16(O[2 * p + 1], pa, make_uint2(vv0[p].z, vv0[p].w));
            }
        }
#pragma unroll
        for (int kt = 1; kt < 4; kt++) {
            uint4 pa = make_uint4(plo[2 * kt], phi[2 * kt], plo[2 * kt + 1], phi[2 * kt + 1]);
            const unsigned* vb2 = vpb + (((size_t)(((j0 >> 4) + kt) << 2)) << 7) + (lane << 2);
#pragma unroll
            for (int p = 0; p < 4; p++) {
                uint4 vv = *(const uint4*)(vb2 + (p << 7));
                mma16(O[2 * p], pa, make_uint2(vv.x, vv.y));
                mma16(O[2 * p + 1], pa, make_uint2(vv.z, vv.w));
            }
        }
        __syncwarp();
    }

    // normalize + write ctx as A-perm bf16
    float inv0 = 1.f / rl0, inv1 = 1.f / rl1;
    int r0g = i0 + (w << 4) + g, r1g = r0g + 8;
#pragma unroll
    for (int dnt = 0; dnt < 8; dnt++) {
        int col = (h << 6) + (dnt << 3) + (tig << 1);
        if (r0g < NL)
            g_ctxp[a_off16(bq * NL + r0g, col, 32)] = bf2(O[dnt].x * inv0, O[dnt].y * inv0);
        if (r1g < NL)
            g_ctxp[a_off16(bq * NL + r1g, col, 32)] = bf2(O[dnt].z * inv1, O[dnt].w * inv1);
    }
}

// ---------------- launch ------------------------------------------------------
extern "C" void kernel_launch(void* const* d_in, const int* in_sizes, int n_in,
                              void* d_out, int out_size) {
    const float* x     = (const float*)d_in[0];
    const float* Wq    = (const float*)d_in[1];
    const float* bq    = (const float*)d_in[2];
    const float* Wk    = (const float*)d_in[3];
    const float* bk    = (const float*)d_in[4];
    const float* Wv    = (const float*)d_in[5];
    const float* bv    = (const float*)d_in[6];
    const float* Wo    = (const float*)d_in[7];
    const float* bo    = (const float*)d_in[8];
    const float* rel   = (const float*)d_in[9];
    const float* gamma = (const float*)d_in[10];
    const float* beta  = (const float*)d_in[11];
    float* out = (float*)d_out;

    prep_kernel<<<1644, 256>>>(Wq, Wk, Wv, Wo, rel, x, gamma, beta);
    gemm2_kernel<<<dim3(8, 125, 3), 128>>>(bq, bk, bv, nullptr, nullptr, 0);  // QKV
    attn_kernel<<<dim3(16, NBH), 128>>>();
    gemm2_kernel<<<dim3(8, 125, 1), 128>>>(bo, nullptr, nullptr, x, out, 1);  // out-proj
}

// round 16
// speedup vs baseline: 1.0215x; 1.0215x over previous
#include <cuda_runtime.h>
#include <cuda_bf16.h>

#define NL 1000
#define ND 512
#define NH 8
#define NDK 64
#define NRR 1999
#define NBH 64
#define LOG2E 1.4426950408889634f

// ---------------- device scratch: pre-permuted bf16 fragment arrays -----------
__device__ unsigned g_xnp [500 * 32 * 128];   // xn  A-perm (8000 x 512)
__device__ unsigned g_ctxp[500 * 32 * 128];   // ctx A-perm (8000 x 512)
__device__ unsigned g_wp  [4 * 131072];       // W   B-perm (512k x 512n) x4
__device__ unsigned g_qp  [NBH * 32768];      // q per bh: A-perm (1024 x 64)
__device__ unsigned g_kp  [NBH * 32768];      // k per bh: pair-packed B (k=d, n=j)
__device__ unsigned g_vp  [NBH * 32768];      // v per bh: pair-packed B (k=j, n=d)
__device__ unsigned g_relp[4 * 136 * 128];    // rel*log2e pair-packed B (k=d, n=u+72)

// ---------------- helpers -----------------------------------------------------
__device__ __forceinline__ unsigned bf2(float lo, float hi) {
    unsigned r;
    asm("cvt.rn.bf16x2.f32 %0, %1, %2;" : "=r"(r) : "f"(hi), "f"(lo));
    return r;
}
__device__ __forceinline__ float ex2f(float x) {
    float r;
    asm("ex2.approx.ftz.f32 %0, %1;" : "=f"(r) : "f"(x));
    return r;
}
__device__ __forceinline__ void mma16(float4& d, uint4 a, uint2 b) {
    asm volatile(
        "mma.sync.aligned.m16n8k16.row.col.f32.bf16.bf16.f32 "
        "{%0,%1,%2,%3}, {%4,%5,%6,%7}, {%8,%9}, {%0,%1,%2,%3};\n"
        : "+f"(d.x), "+f"(d.y), "+f"(d.z), "+f"(d.w)
        : "r"(a.x), "r"(a.y), "r"(a.z), "r"(a.w), "r"(b.x), "r"(b.y));
}
// A tile 16x16 (u32 = bf16x2 over k)
__device__ __forceinline__ int a_off16(int m, int k, int nkt16) {
    return (((m >> 4) * nkt16 + (k >> 4)) << 7) +
           ((((m & 7) << 2) + ((k & 7) >> 1)) << 2) + ((m >> 3) & 1) + (((k >> 3) & 1) << 1);
}
// classic B tile 16x8 (for g_wp only)
__device__ __forceinline__ int b_off16(int k, int n, int nnt) {
    return (((k >> 4) * nnt + (n >> 3)) << 6) +
           ((((n & 7) << 2) + ((k & 7) >> 1)) << 1) + ((k >> 3) & 1);
}
// pair-packed B: two n8 tiles per 128-word block, per-lane 4 words
__device__ __forceinline__ int bp_off(int k, int n, int NP) {
    return (((k >> 4) * NP + (n >> 4)) << 7) +
           ((((n & 7) << 2) + ((k & 7) >> 1)) << 2) + (((n >> 3) & 1) << 1) + ((k >> 3) & 1);
}

// ---------------- fused preamble (lean): wconv + relconv + zfill + warp-LN ----
__global__ void prep_kernel(const float* __restrict__ W0, const float* __restrict__ W1,
                            const float* __restrict__ W2, const float* __restrict__ W3,
                            const float* __restrict__ rel,
                            const float* __restrict__ x,
                            const float* __restrict__ gamma,
                            const float* __restrict__ beta) {
    int bid = blockIdx.x;
    if (bid < 512) {
        int gt = (bid << 8) + threadIdx.x;            // 131072 threads
        int widx = gt >> 15;
        const float* W = (widx == 0) ? W0 : (widx == 1) ? W1 : (widx == 2) ? W2 : W3;
        int t = gt & 32767;
        int n = t >> 6, k0 = (t & 63) << 3;
        float4 va = *(const float4*)&W[(size_t)n * ND + k0];
        float4 vb = *(const float4*)&W[(size_t)n * ND + k0 + 4];
        unsigned* wp = g_wp + widx * 131072;
        wp[b_off16(k0 + 0, n, 64)] = bf2(va.x, va.y);
        wp[b_off16(k0 + 2, n, 64)] = bf2(va.z, va.w);
        wp[b_off16(k0 + 4, n, 64)] = bf2(vb.x, vb.y);
        wp[b_off16(k0 + 6, n, 64)] = bf2(vb.z, vb.w);
    } else if (bid < 580) {
        int t = ((bid - 512) << 8) + threadIdx.x;     // 17408 threads
        int u = t >> 3, k0 = (t & 7) << 3;
        int ua = u - 72;
        float4 va = make_float4(0.f, 0.f, 0.f, 0.f);
        float4 vb = make_float4(0.f, 0.f, 0.f, 0.f);
        if (ua >= 0 && ua < NRR) {
            va = *(const float4*)&rel[(size_t)ua * NDK + k0];
            vb = *(const float4*)&rel[(size_t)ua * NDK + k0 + 4];
        }
        g_relp[bp_off(k0 + 0, u, 136)] = bf2(va.x * LOG2E, va.y * LOG2E);
        g_relp[bp_off(k0 + 2, u, 136)] = bf2(va.z * LOG2E, va.w * LOG2E);
        g_relp[bp_off(k0 + 4, u, 136)] = bf2(vb.x * LOG2E, vb.y * LOG2E);
        g_relp[bp_off(k0 + 6, u, 136)] = bf2(vb.z * LOG2E, vb.w * LOG2E);
    } else if (bid < 644) {
        int bh = bid - 580;
        for (int f = threadIdx.x; f < 768; f += 256) {
            int m = 1000 + (f >> 5);
            int k = (f & 31) << 1;
            g_qp[bh * 32768 + a_off16(m, k, 4)] = 0;
            g_kp[bh * 32768 + bp_off(k, m, 64)] = 0;
            int k0v = 1000 + ((f >> 6) << 1);
            int dv = f & 63;
            g_vp[bh * 32768 + bp_off(k0v, dv, 4)] = 0;
        }
    } else {
        // layernorm: warp per row, 8 rows per 256-thread block
        int lane = threadIdx.x & 31, wp = threadIdx.x >> 5;
        int row = ((bid - 644) << 3) + wp;
        const float4* xr = (const float4*)(x + (size_t)row * ND);
        float4 v[4];
#pragma unroll
        for (int i = 0; i < 4; i++) v[i] = xr[lane + (i << 5)];
        float s = 0.f;
#pragma unroll
        for (int i = 0; i < 4; i++) s += v[i].x + v[i].y + v[i].z + v[i].w;
#pragma unroll
        for (int o = 16; o; o >>= 1) s += __shfl_xor_sync(0xffffffffu, s, o);
        float mean = s * (1.0f / ND);
        float s2 = 0.f;
#pragma unroll
        for (int i = 0; i < 4; i++) {
            float a = v[i].x - mean, b = v[i].y - mean;
            float c = v[i].z - mean, d = v[i].w - mean;
            s2 += a * a + b * b + c * c + d * d;
        }
#pragma unroll
        for (int o = 16; o; o >>= 1) s2 += __shfl_xor_sync(0xffffffffu, s2, o);
        float inv = rsqrtf(s2 * (1.0f / ND) + 1e-5f);
#pragma unroll
        for (int i = 0; i < 4; i++) {
            float4 gg = ((const float4*)gamma)[lane + (i << 5)];
            float4 bt = ((const float4*)beta)[lane + (i << 5)];
            int k0 = (lane + (i << 5)) << 2;
            float o0 = (v[i].x - mean) * inv * gg.x + bt.x;
            float o1 = (v[i].y - mean) * inv * gg.y + bt.y;
            float o2 = (v[i].z - mean) * inv * gg.z + bt.z;
            float o3 = (v[i].w - mean) * inv * gg.w + bt.w;
            g_xnp[a_off16(row, k0, 32)] = bf2(o0, o1);
            g_xnp[a_off16(row, k0 + 2, 32)] = bf2(o2, o3);
        }
    }
}

// ---------------- streaming bf16 GEMM: depth-2 pipeline (R14 proven) ----------
__global__ void __launch_bounds__(128) gemm2_kernel(
    const float* __restrict__ b0, const float* __restrict__ b1,
    const float* __restrict__ b2, const float* __restrict__ resid,
    float* __restrict__ Cf, int outproj) {
    const int tid = threadIdx.x, lane = tid & 31, warp = tid >> 5;
    const int wm = warp >> 1, wn = warp & 1, g = lane >> 2, tig = lane & 3;
    const int m0 = blockIdx.y * 64, n0 = blockIdx.x * 64;
    const int z = blockIdx.z;
    const int mode = outproj ? 1 : (z == 0 ? 0 : (z == 1 ? 2 : 3));
    const int widx = outproj ? 3 : z;
    const float* bias = outproj ? b0 : (z == 0 ? b0 : (z == 1 ? b1 : b2));
    const unsigned* Ap = outproj ? g_ctxp : g_xnp;
    const unsigned* Ab = Ap + (size_t)(((m0 + wm * 32) >> 4) * 32) * 128 + (lane << 2);
    const unsigned* Bb = g_wp + (size_t)widx * 131072 + (size_t)((n0 >> 3) + wn * 4) * 64 + (lane << 1);

    float4 acc[2][4] = {};
    uint4 a[2][2];
    uint2 b[2][4];
    a[0][0] = *(const uint4*)(Ab);
    a[0][1] = *(const uint4*)(Ab + 4096);
#pragma unroll
    for (int j = 0; j < 4; j++) b[0][j] = *(const uint2*)(Bb + j * 64);
#pragma unroll
    for (int kt = 0; kt < 32; kt++) {
        int cur = kt & 1, nxt = cur ^ 1;
        if (kt < 31) {
            a[nxt][0] = *(const uint4*)(Ab + (kt + 1) * 128);
            a[nxt][1] = *(const uint4*)(Ab + 4096 + (kt + 1) * 128);
#pragma unroll
            for (int j = 0; j < 4; j++)
                b[nxt][j] = *(const uint2*)(Bb + (size_t)(kt + 1) * 4096 + j * 64);
        }
#pragma unroll
        for (int j = 0; j < 4; j++) {
            mma16(acc[0][j], a[cur][0], b[cur][j]);
            mma16(acc[1][j], a[cur][1], b[cur][j]);
        }
    }

    const float KS = 0.125f * LOG2E;
#pragma unroll
    for (int i = 0; i < 2; i++)
#pragma unroll
        for (int j = 0; j < 4; j++) {
            int col = n0 + wn * 32 + j * 8 + (tig << 1);
            float2 bb = *(const float2*)&bias[col];
            float4 c = acc[i][j];
            float cx = c.x + bb.x, cy = c.y + bb.y;
            float cz = c.z + bb.x, cw = c.w + bb.y;
            int r0 = m0 + wm * 32 + i * 16 + g, r1 = r0 + 8;
            if (mode == 1) {
                size_t o0 = (size_t)r0 * ND + col, o1 = (size_t)r1 * ND + col;
                float2 rr0 = *(const float2*)&resid[o0];
                float2 rr1 = *(const float2*)&resid[o1];
                *(float2*)&Cf[o0] = make_float2(cx + rr0.x, cy + rr0.y);
                *(float2*)&Cf[o1] = make_float2(cz + rr1.x, cw + rr1.y);
            } else if (mode == 3) {
                float ox = __shfl_xor_sync(0xffffffffu, cx, 4);
                float oy = __shfl_xor_sync(0xffffffffu, cy, 4);
                float oz = __shfl_xor_sync(0xffffffffu, cz, 4);
                float ow = __shfl_xor_sync(0xffffffffu, cw, 4);
                if (!(g & 1)) {
                    int h = col >> 6, d = col & 63;
                    int b0i = r0 / NL, l0 = r0 - b0i * NL;
                    int b1i = r1 / NL, l1 = r1 - b1i * NL;
                    unsigned* vp0 = g_vp + (b0i * NH + h) * 32768;
                    unsigned* vp1 = g_vp + (b1i * NH + h) * 32768;
                    vp0[bp_off(l0, d, 4)] = bf2(cx, ox);
                    vp0[bp_off(l0, d + 1, 4)] = bf2(cy, oy);
                    vp1[bp_off(l1, d, 4)] = bf2(cz, oz);
                    vp1[bp_off(l1, d + 1, 4)] = bf2(cw, ow);
                }
            } else {
                int h = col >> 6, d = col & 63;
                int b0i = r0 / NL, l0 = r0 - b0i * NL;
                int b1i = r1 / NL, l1 = r1 - b1i * NL;
                int bh0 = b0i * NH + h, bh1 = b1i * NH + h;
                if (mode == 0) {
                    g_qp[bh0 * 32768 + a_off16(l0, d, 4)] = bf2(cx, cy);
                    g_qp[bh1 * 32768 + a_off16(l1, d, 4)] = bf2(cz, cw);
                } else {
                    g_kp[bh0 * 32768 + bp_off(d, l0, 64)] = bf2(cx * KS, cy * KS);
                    g_kp[bh1 * 32768 + bp_off(d, l1, 64)] = bf2(cz * KS, cw * KS);
                }
            }
        }
}

// ---------------- flash attention: warp-exclusive rows, pair-packed loads -----
#define S2STRIDE 19

__global__ void __launch_bounds__(128) attn_kernel() {
    __shared__ float S2all[4 * 128 * S2STRIDE];

    const int it = blockIdx.x, bh = blockIdx.y;
    const int bq = bh >> 3, h = bh & 7;
    const int i0 = it << 6;
    const int tid = threadIdx.x;
    const int lane = tid & 31, w = tid >> 5;
    const int g = lane >> 2, tig = lane & 3;
    float* S2w = S2all + w * 128 * S2STRIDE;

    const unsigned* qpb = g_qp + bh * 32768;
    const unsigned* kpb = g_kp + bh * 32768;
    const unsigned* vpb = g_vp + bh * 32768;

    uint4 qf[4];
#pragma unroll
    for (int kt = 0; kt < 4; kt++)
        qf[kt] = *(const uint4*)(qpb + (size_t)(((it << 2) + w) * 4 + kt) * 128 + (lane << 2));

    float rm0 = -1e30f, rm1 = -1e30f, rl0 = 0.f, rl1 = 0.f;
    float4 O[8] = {};

    const int nboff = (1056 - i0 - (w << 4)) >> 3;

    // warm the ring: v in [0, 80) -> 5 tile-pairs
#pragma unroll
    for (int p = 0; p < 5; p++) {
        int pair = p + (nboff >> 1);
        float4 a0 = make_float4(0.f, 0.f, 0.f, 0.f);
        float4 a1 = make_float4(0.f, 0.f, 0.f, 0.f);
#pragma unroll
        for (int kt = 0; kt < 4; kt++) {
            uint4 bb = *(const uint4*)(g_relp + (((size_t)kt * 136 + pair) << 7) + (lane << 2));
            mma16(a0, qf[kt], make_uint2(bb.x, bb.y));
            mma16(a1, qf[kt], make_uint2(bb.z, bb.w));
        }
        int sl = (p << 4) + (tig << 1);
        S2w[sl * S2STRIDE + g] = a0.x;
        S2w[(sl + 1) * S2STRIDE + g] = a0.y;
        S2w[sl * S2STRIDE + g + 8] = a0.z;
        S2w[(sl + 1) * S2STRIDE + g + 8] = a0.w;
        S2w[(sl + 8) * S2STRIDE + g] = a1.x;
        S2w[(sl + 9) * S2STRIDE + g] = a1.y;
        S2w[(sl + 8) * S2STRIDE + g + 8] = a1.z;
        S2w[(sl + 9) * S2STRIDE + g + 8] = a1.w;
    }
    __syncwarp();

    for (int jt = 0; jt < 16; jt++) {
        const int j0 = jt << 6;

        // S2: new band tiles v in [j0+16, j0+80) -> 4 tile-pairs into ring
#pragma unroll
        for (int p = 0; p < 4; p++) {
            int v8 = ((j0 + 16) >> 3) + (p << 1);
            int pair = (v8 + nboff) >> 1;
            float4 a0 = make_float4(0.f, 0.f, 0.f, 0.f);
            float4 a1 = make_float4(0.f, 0.f, 0.f, 0.f);
#pragma unroll
            for (int kt = 0; kt < 4; kt++) {
                uint4 bb = *(const uint4*)(g_relp + (((size_t)kt * 136 + pair) << 7) + (lane << 2));
                mma16(a0, qf[kt], make_uint2(bb.x, bb.y));
                mma16(a1, qf[kt], make_uint2(bb.z, bb.w));
            }
            int sl = ((j0 + 16 + (p << 4)) & 127) + (tig << 1);
            S2w[sl * S2STRIDE + g] = a0.x;
            S2w[(sl + 1) * S2STRIDE + g] = a0.y;
            S2w[sl * S2STRIDE + g + 8] = a0.z;
            S2w[(sl + 1) * S2STRIDE + g + 8] = a0.w;
            S2w[(sl + 8) * S2STRIDE + g] = a1.x;
            S2w[(sl + 9) * S2STRIDE + g] = a1.y;
            S2w[(sl + 8) * S2STRIDE + g + 8] = a1.z;
            S2w[(sl + 9) * S2STRIDE + g + 8] = a1.w;
        }
        __syncwarp();

        // S1 = Q @ K^T over 4 n8-tile pairs
        float4 s1[8] = {};
#pragma unroll
        for (int kt = 0; kt < 4; kt++) {
#pragma unroll
            for (int p = 0; p < 4; p++) {
                uint4 kk = *(const uint4*)(kpb +
                    (((size_t)(kt * 64 + (j0 >> 4) + p)) << 7) + (lane << 2));
                mma16(s1[2 * p], qf[kt], make_uint2(kk.x, kk.y));
                mma16(s1[2 * p + 1], qf[kt], make_uint2(kk.z, kk.w));
            }
        }

        // gather ring + mask + row max (warp-local)
        float m0 = -1e30f, m1 = -1e30f;
#pragma unroll
        for (int nt = 0; nt < 8; nt++) {
            int c = (nt << 3) + (tig << 1);
            int v0 = j0 + c - g + 15;
            int v1 = v0 - 8;
            s1[nt].x += S2w[(v0 & 127) * S2STRIDE + g];
            s1[nt].y += S2w[((v0 + 1) & 127) * S2STRIDE + g];
            s1[nt].z += S2w[(v1 & 127) * S2STRIDE + g + 8];
            s1[nt].w += S2w[((v1 + 1) & 127) * S2STRIDE + g + 8];
            if (j0 + c >= NL) { s1[nt].x = -1e30f; s1[nt].z = -1e30f; }
            if (j0 + c + 1 >= NL) { s1[nt].y = -1e30f; s1[nt].w = -1e30f; }
            m0 = fmaxf(m0, fmaxf(s1[nt].x, s1[nt].y));
            m1 = fmaxf(m1, fmaxf(s1[nt].z, s1[nt].w));
        }
        m0 = fmaxf(m0, __shfl_xor_sync(0xffffffffu, m0, 1));
        m0 = fmaxf(m0, __shfl_xor_sync(0xffffffffu, m0, 2));
        m1 = fmaxf(m1, __shfl_xor_sync(0xffffffffu, m1, 1));
        m1 = fmaxf(m1, __shfl_xor_sync(0xffffffffu, m1, 2));

        // prefetch kt=0 V fragments — latency hides under the exp2/shfl work below
        uint4 vv0[4];
#pragma unroll
        for (int p = 0; p < 4; p++)
            vv0[p] = *(const uint4*)(vpb + (((size_t)((j0 >> 4) << 2)) << 7) +
                                     (p << 7) + (lane << 2));

        float mn0 = fmaxf(rm0, m0), mn1 = fmaxf(rm1, m1);
        float a0 = ex2f(rm0 - mn0), a1 = ex2f(rm1 - mn1);
        rm0 = mn0; rm1 = mn1;

        unsigned plo[8], phi[8];
        float s0 = 0.f, sh = 0.f;
#pragma unroll
        for (int nt = 0; nt < 8; nt++) {
            float e00 = ex2f(s1[nt].x - mn0), e01 = ex2f(s1[nt].y - mn0);
            float e10 = ex2f(s1[nt].z - mn1), e11 = ex2f(s1[nt].w - mn1);
            plo[nt] = bf2(e00, e01);
            phi[nt] = bf2(e10, e11);
            s0 += e00 + e01;
            sh += e10 + e11;
        }
        s0 += __shfl_xor_sync(0xffffffffu, s0, 1);
        s0 += __shfl_xor_sync(0xffffffffu, s0, 2);
        sh += __shfl_xor_sync(0xffffffffu, sh, 1);
        sh += __shfl_xor_sync(0xffffffffu, sh, 2);
        rl0 = rl0 * a0 + s0;
        rl1 = rl1 * a1 + sh;

        // O rescale, then O += P @ V
#pragma unroll
        for (int dnt = 0; dnt < 8; dnt++) {
            O[dnt].x *= a0; O[dnt].y *= a0;
            O[dnt].z *= a1; O[dnt].w *= a1;
        }
        {
            uint4 pa = make_uint4(plo[0], phi[0], plo[1], phi[1]);
#pragma unroll
            for (int p = 0; p < 4; p++) {
                mma16(O[2 * p], pa, make_uint2(vv0[p].x, vv0[p].y));
                mma16(O[2 * p + 1], pa, make_uint2(vv0[p].z, vv0[p].w));
            }
        }
#pragma unroll
        for (int kt = 1; kt < 4; kt++) {
            uint4 pa = make_uint4(plo[2 * kt], phi[2 * kt], plo[2 * kt + 1], phi[2 * kt + 1]);
            const unsigned* vb2 = vpb + (((size_t)(((j0 >> 4) + kt) << 2)) << 7) + (lane << 2);
#pragma unroll
            for (int p = 0; p < 4; p++) {
                uint4 vv = *(const uint4*)(vb2 + (p << 7));
                mma16(O[2 * p], pa, make_uint2(vv.x, vv.y));
                mma16(O[2 * p + 1], pa, make_uint2(vv.z, vv.w));
            }
        }
        __syncwarp();
    }

    // normalize + write ctx as A-perm bf16
    float inv0 = 1.f / rl0, inv1 = 1.f / rl1;
    int r0g = i0 + (w << 4) + g, r1g = r0g + 8;
#pragma unroll
    for (int dnt = 0; dnt < 8; dnt++) {
        int col = (h << 6) + (dnt << 3) + (tig << 1);
        if (r0g < NL)
            g_ctxp[a_off16(bq * NL + r0g, col, 32)] = bf2(O[dnt].x * inv0, O[dnt].y * inv0);
        if (r1g < NL)
            g_ctxp[a_off16(bq * NL + r1g, col, 32)] = bf2(O[dnt].z * inv1, O[dnt].w * inv1);
    }
}

// ---------------- launch ------------------------------------------------------
extern "C" void kernel_launch(void* const* d_in, const int* in_sizes, int n_in,
                              void* d_out, int out_size) {
    const float* x     = (const float*)d_in[0];
    const float* Wq    = (const float*)d_in[1];
    const float* bq    = (const float*)d_in[2];
    const float* Wk    = (const float*)d_in[3];
    const float* bk    = (const float*)d_in[4];
    const float* Wv    = (const float*)d_in[5];
    const float* bv    = (const float*)d_in[6];
    const float* Wo    = (const float*)d_in[7];
    const float* bo    = (const float*)d_in[8];
    const float* rel   = (const float*)d_in[9];
    const float* gamma = (const float*)d_in[10];
    const float* beta  = (const float*)d_in[11];
    float* out = (float*)d_out;

    prep_kernel<<<1644, 256>>>(Wq, Wk, Wv, Wo, rel, x, gamma, beta);
    gemm2_kernel<<<dim3(8, 125, 3), 128>>>(bq, bk, bv, nullptr, nullptr, 0);  // QKV
    attn_kernel<<<dim3(16, NBH), 128>>>();
    gemm2_kernel<<<dim3(8, 125, 1), 128>>>(bo, nullptr, nullptr, x, out, 1);  // out-proj
}

// round 17
// speedup vs baseline: 1.1465x; 1.1225x over previous
#include <cuda_runtime.h>
#include <cuda_bf16.h>
#include <cuda_fp16.h>

#define NL 1000
#define ND 512
#define NH 8
#define NDK 64
#define NRR 1999
#define NBH 64
#define LOG2E 1.4426950408889634f

// ---------------- device scratch: pre-permuted fragment arrays ----------------
__device__ unsigned g_xnp [500 * 32 * 128];   // xn  A-perm bf16 (8000 x 512)
__device__ unsigned g_ctxp[500 * 32 * 128];   // ctx A-perm bf16 (8000 x 512)
__device__ unsigned g_wp  [4 * 131072];       // W   B-perm bf16 x4
__device__ unsigned g_qp  [NBH * 32768];      // q per bh: A-perm bf16 (1024 x 64)
__device__ unsigned g_kp  [NBH * 32768];      // k per bh: pair-packed B bf16 (k=d, n=j)
__device__ unsigned g_vp  [NBH * 32768];      // v per bh: pair-packed B **f16** (k=j, n=d)
__device__ unsigned g_relp[4 * 136 * 128];    // rel*log2e pair-packed B bf16 (k=d, n=u+72)

// ---------------- helpers -----------------------------------------------------
__device__ __forceinline__ unsigned bf2(float lo, float hi) {
    unsigned r;
    asm("cvt.rn.bf16x2.f32 %0, %1, %2;" : "=r"(r) : "f"(hi), "f"(lo));
    return r;
}
__device__ __forceinline__ float ex2f(float x) {
    float r;
    asm("ex2.approx.ftz.f32 %0, %1;" : "=f"(r) : "f"(x));
    return r;
}
// pack two f32 -> f16x2, then exp2 both halves in one MUFU op
__device__ __forceinline__ unsigned hexp2p(float lo, float hi) {
    __half2 h = __floats2half2_rn(lo, hi);
    h = h2exp2(h);
    return *(unsigned*)&h;
}
__device__ __forceinline__ unsigned hpack(float lo, float hi) {
    __half2 h = __floats2half2_rn(lo, hi);
    return *(unsigned*)&h;
}
// bf16 mma
__device__ __forceinline__ void mma16(float4& d, uint4 a, uint2 b) {
    asm volatile(
        "mma.sync.aligned.m16n8k16.row.col.f32.bf16.bf16.f32 "
        "{%0,%1,%2,%3}, {%4,%5,%6,%7}, {%8,%9}, {%0,%1,%2,%3};\n"
        : "+f"(d.x), "+f"(d.y), "+f"(d.z), "+f"(d.w)
        : "r"(a.x), "r"(a.y), "r"(a.z), "r"(a.w), "r"(b.x), "r"(b.y));
}
// f16 mma (P @ V and row-sum)
__device__ __forceinline__ void mma16h(float4& d, uint4 a, uint2 b) {
    asm volatile(
        "mma.sync.aligned.m16n8k16.row.col.f32.f16.f16.f32 "
        "{%0,%1,%2,%3}, {%4,%5,%6,%7}, {%8,%9}, {%0,%1,%2,%3};\n"
        : "+f"(d.x), "+f"(d.y), "+f"(d.z), "+f"(d.w)
        : "r"(a.x), "r"(a.y), "r"(a.z), "r"(a.w), "r"(b.x), "r"(b.y));
}
// A tile 16x16 (u32 = 16x2 over k)
__device__ __forceinline__ int a_off16(int m, int k, int nkt16) {
    return (((m >> 4) * nkt16 + (k >> 4)) << 7) +
           ((((m & 7) << 2) + ((k & 7) >> 1)) << 2) + ((m >> 3) & 1) + (((k >> 3) & 1) << 1);
}
// classic B tile 16x8 (for g_wp only)
__device__ __forceinline__ int b_off16(int k, int n, int nnt) {
    return (((k >> 4) * nnt + (n >> 3)) << 6) +
           ((((n & 7) << 2) + ((k & 7) >> 1)) << 1) + ((k >> 3) & 1);
}
// pair-packed B: two n8 tiles per 128-word block, per-lane 4 words
__device__ __forceinline__ int bp_off(int k, int n, int NP) {
    return (((k >> 4) * NP + (n >> 4)) << 7) +
           ((((n & 7) << 2) + ((k & 7) >> 1)) << 2) + (((n >> 3) & 1) << 1) + ((k >> 3) & 1);
}

// ---------------- fused preamble (lean): wconv + relconv + zfill + warp-LN ----
__global__ void prep_kernel(const float* __restrict__ W0, const float* __restrict__ W1,
                            const float* __restrict__ W2, const float* __restrict__ W3,
                            const float* __restrict__ rel,
                            const float* __restrict__ x,
                            const float* __restrict__ gamma,
                            const float* __restrict__ beta) {
    int bid = blockIdx.x;
    if (bid < 512) {
        int gt = (bid << 8) + threadIdx.x;
        int widx = gt >> 15;
        const float* W = (widx == 0) ? W0 : (widx == 1) ? W1 : (widx == 2) ? W2 : W3;
        int t = gt & 32767;
        int n = t >> 6, k0 = (t & 63) << 3;
        float4 va = *(const float4*)&W[(size_t)n * ND + k0];
        float4 vb = *(const float4*)&W[(size_t)n * ND + k0 + 4];
        unsigned* wp = g_wp + widx * 131072;
        wp[b_off16(k0 + 0, n, 64)] = bf2(va.x, va.y);
        wp[b_off16(k0 + 2, n, 64)] = bf2(va.z, va.w);
        wp[b_off16(k0 + 4, n, 64)] = bf2(vb.x, vb.y);
        wp[b_off16(k0 + 6, n, 64)] = bf2(vb.z, vb.w);
    } else if (bid < 580) {
        int t = ((bid - 512) << 8) + threadIdx.x;
        int u = t >> 3, k0 = (t & 7) << 3;
        int ua = u - 72;
        float4 va = make_float4(0.f, 0.f, 0.f, 0.f);
        float4 vb = make_float4(0.f, 0.f, 0.f, 0.f);
        if (ua >= 0 && ua < NRR) {
            va = *(const float4*)&rel[(size_t)ua * NDK + k0];
            vb = *(const float4*)&rel[(size_t)ua * NDK + k0 + 4];
        }
        g_relp[bp_off(k0 + 0, u, 136)] = bf2(va.x * LOG2E, va.y * LOG2E);
        g_relp[bp_off(k0 + 2, u, 136)] = bf2(va.z * LOG2E, va.w * LOG2E);
        g_relp[bp_off(k0 + 4, u, 136)] = bf2(vb.x * LOG2E, vb.y * LOG2E);
        g_relp[bp_off(k0 + 6, u, 136)] = bf2(vb.z * LOG2E, vb.w * LOG2E);
    } else if (bid < 644) {
        int bh = bid - 580;
        for (int f = threadIdx.x; f < 768; f += 256) {
            int m = 1000 + (f >> 5);
            int k = (f & 31) << 1;
            g_qp[bh * 32768 + a_off16(m, k, 4)] = 0;
            g_kp[bh * 32768 + bp_off(k, m, 64)] = 0;
            int k0v = 1000 + ((f >> 6) << 1);
            int dv = f & 63;
            g_vp[bh * 32768 + bp_off(k0v, dv, 4)] = 0;
        }
    } else {
        int lane = threadIdx.x & 31, wp = threadIdx.x >> 5;
        int row = ((bid - 644) << 3) + wp;
        const float4* xr = (const float4*)(x + (size_t)row * ND);
        float4 v[4];
#pragma unroll
        for (int i = 0; i < 4; i++) v[i] = xr[lane + (i << 5)];
        float s = 0.f;
#pragma unroll
        for (int i = 0; i < 4; i++) s += v[i].x + v[i].y + v[i].z + v[i].w;
#pragma unroll
        for (int o = 16; o; o >>= 1) s += __shfl_xor_sync(0xffffffffu, s, o);
        float mean = s * (1.0f / ND);
        float s2 = 0.f;
#pragma unroll
        for (int i = 0; i < 4; i++) {
            float a = v[i].x - mean, b = v[i].y - mean;
            float c = v[i].z - mean, d = v[i].w - mean;
            s2 += a * a + b * b + c * c + d * d;
        }
#pragma unroll
        for (int o = 16; o; o >>= 1) s2 += __shfl_xor_sync(0xffffffffu, s2, o);
        float inv = rsqrtf(s2 * (1.0f / ND) + 1e-5f);
#pragma unroll
        for (int i = 0; i < 4; i++) {
            float4 gg = ((const float4*)gamma)[lane + (i << 5)];
            float4 bt = ((const float4*)beta)[lane + (i << 5)];
            int k0 = (lane + (i << 5)) << 2;
            float o0 = (v[i].x - mean) * inv * gg.x + bt.x;
            float o1 = (v[i].y - mean) * inv * gg.y + bt.y;
            float o2 = (v[i].z - mean) * inv * gg.z + bt.z;
            float o3 = (v[i].w - mean) * inv * gg.w + bt.w;
            g_xnp[a_off16(row, k0, 32)] = bf2(o0, o1);
            g_xnp[a_off16(row, k0 + 2, 32)] = bf2(o2, o3);
        }
    }
}

// ---------------- streaming bf16 GEMM: depth-2 pipeline (R14 proven) ----------
__global__ void __launch_bounds__(128) gemm2_kernel(
    const float* __restrict__ b0, const float* __restrict__ b1,
    const float* __restrict__ b2, const float* __restrict__ resid,
    float* __restrict__ Cf, int outproj) {
    const int tid = threadIdx.x, lane = tid & 31, warp = tid >> 5;
    const int wm = warp >> 1, wn = warp & 1, g = lane >> 2, tig = lane & 3;
    const int m0 = blockIdx.y * 64, n0 = blockIdx.x * 64;
    const int z = blockIdx.z;
    const int mode = outproj ? 1 : (z == 0 ? 0 : (z == 1 ? 2 : 3));
    const int widx = outproj ? 3 : z;
    const float* bias = outproj ? b0 : (z == 0 ? b0 : (z == 1 ? b1 : b2));
    const unsigned* Ap = outproj ? g_ctxp : g_xnp;
    const unsigned* Ab = Ap + (size_t)(((m0 + wm * 32) >> 4) * 32) * 128 + (lane << 2);
    const unsigned* Bb = g_wp + (size_t)widx * 131072 + (size_t)((n0 >> 3) + wn * 4) * 64 + (lane << 1);

    float4 acc[2][4] = {};
    uint4 a[2][2];
    uint2 b[2][4];
    a[0][0] = *(const uint4*)(Ab);
    a[0][1] = *(const uint4*)(Ab + 4096);
#pragma unroll
    for (int j = 0; j < 4; j++) b[0][j] = *(const uint2*)(Bb + j * 64);
#pragma unroll
    for (int kt = 0; kt < 32; kt++) {
        int cur = kt & 1, nxt = cur ^ 1;
        if (kt < 31) {
            a[nxt][0] = *(const uint4*)(Ab + (kt + 1) * 128);
            a[nxt][1] = *(const uint4*)(Ab + 4096 + (kt + 1) * 128);
#pragma unroll
            for (int j = 0; j < 4; j++)
                b[nxt][j] = *(const uint2*)(Bb + (size_t)(kt + 1) * 4096 + j * 64);
        }
#pragma unroll
        for (int j = 0; j < 4; j++) {
            mma16(acc[0][j], a[cur][0], b[cur][j]);
            mma16(acc[1][j], a[cur][1], b[cur][j]);
        }
    }

    const float KS = 0.125f * LOG2E;
#pragma unroll
    for (int i = 0; i < 2; i++)
#pragma unroll
        for (int j = 0; j < 4; j++) {
            int col = n0 + wn * 32 + j * 8 + (tig << 1);
            float2 bb = *(const float2*)&bias[col];
            float4 c = acc[i][j];
            float cx = c.x + bb.x, cy = c.y + bb.y;
            float cz = c.z + bb.x, cw = c.w + bb.y;
            int r0 = m0 + wm * 32 + i * 16 + g, r1 = r0 + 8;
            if (mode == 1) {
                size_t o0 = (size_t)r0 * ND + col, o1 = (size_t)r1 * ND + col;
                float2 rr0 = *(const float2*)&resid[o0];
                float2 rr1 = *(const float2*)&resid[o1];
                *(float2*)&Cf[o0] = make_float2(cx + rr0.x, cy + rr0.y);
                *(float2*)&Cf[o1] = make_float2(cz + rr1.x, cw + rr1.y);
            } else if (mode == 3) {
                // V: pair rows j, j+1 via shfl; store as f16x2 for f16 PV mma
                float ox = __shfl_xor_sync(0xffffffffu, cx, 4);
                float oy = __shfl_xor_sync(0xffffffffu, cy, 4);
                float oz = __shfl_xor_sync(0xffffffffu, cz, 4);
                float ow = __shfl_xor_sync(0xffffffffu, cw, 4);
                if (!(g & 1)) {
                    int h = col >> 6, d = col & 63;
                    int b0i = r0 / NL, l0 = r0 - b0i * NL;
                    int b1i = r1 / NL, l1 = r1 - b1i * NL;
                    unsigned* vp0 = g_vp + (b0i * NH + h) * 32768;
                    unsigned* vp1 = g_vp + (b1i * NH + h) * 32768;
                    vp0[bp_off(l0, d, 4)] = hpack(cx, ox);
                    vp0[bp_off(l0, d + 1, 4)] = hpack(cy, oy);
                    vp1[bp_off(l1, d, 4)] = hpack(cz, oz);
                    vp1[bp_off(l1, d + 1, 4)] = hpack(cw, ow);
                }
            } else {
                int h = col >> 6, d = col & 63;
                int b0i = r0 / NL, l0 = r0 - b0i * NL;
                int b1i = r1 / NL, l1 = r1 - b1i * NL;
                int bh0 = b0i * NH + h, bh1 = b1i * NH + h;
                if (mode == 0) {
                    g_qp[bh0 * 32768 + a_off16(l0, d, 4)] = bf2(cx, cy);
                    g_qp[bh1 * 32768 + a_off16(l1, d, 4)] = bf2(cz, cw);
                } else {
                    g_kp[bh0 * 32768 + bp_off(d, l0, 64)] = bf2(cx * KS, cy * KS);
                    g_kp[bh1 * 32768 + bp_off(d, l1, 64)] = bf2(cz * KS, cw * KS);
                }
            }
        }
}

// ---------------- flash attention: f16 softmax path + tensor-core row sums ----
#define S2STRIDE 19

__global__ void __launch_bounds__(128) attn_kernel() {
    __shared__ float S2all[4 * 128 * S2STRIDE];

    const int it = blockIdx.x, bh = blockIdx.y;
    const int bq = bh >> 3, h = bh & 7;
    const int i0 = it << 6;
    const int tid = threadIdx.x;
    const int lane = tid & 31, w = tid >> 5;
    const int g = lane >> 2, tig = lane & 3;
    float* S2w = S2all + w * 128 * S2STRIDE;

    const unsigned* qpb = g_qp + bh * 32768;
    const unsigned* kpb = g_kp + bh * 32768;
    const unsigned* vpb = g_vp + bh * 32768;

    uint4 qf[4];
#pragma unroll
    for (int kt = 0; kt < 4; kt++)
        qf[kt] = *(const uint4*)(qpb + (size_t)(((it << 2) + w) * 4 + kt) * 128 + (lane << 2));

    // ones B-fragment (f16): col 0 = 1.0 -> lanes 0..3, both regs/halves
    const uint2 bones = (lane < 4) ? make_uint2(0x3C003C00u, 0x3C003C00u)
                                   : make_uint2(0u, 0u);

    float rm0 = -1e30f, rm1 = -1e30f, rl0 = 0.f, rl1 = 0.f;
    float4 O[8] = {};

    const int nboff = (1056 - i0 - (w << 4)) >> 3;

    // warm the ring: v in [0, 80) -> 5 tile-pairs
#pragma unroll
    for (int p = 0; p < 5; p++) {
        int pair = p + (nboff >> 1);
        float4 a0 = make_float4(0.f, 0.f, 0.f, 0.f);
        float4 a1 = make_float4(0.f, 0.f, 0.f, 0.f);
#pragma unroll
        for (int kt = 0; kt < 4; kt++) {
            uint4 bb = *(const uint4*)(g_relp + (((size_t)kt * 136 + pair) << 7) + (lane << 2));
            mma16(a0, qf[kt], make_uint2(bb.x, bb.y));
            mma16(a1, qf[kt], make_uint2(bb.z, bb.w));
        }
        int sl = (p << 4) + (tig << 1);
        S2w[sl * S2STRIDE + g] = a0.x;
        S2w[(sl + 1) * S2STRIDE + g] = a0.y;
        S2w[sl * S2STRIDE + g + 8] = a0.z;
        S2w[(sl + 1) * S2STRIDE + g + 8] = a0.w;
        S2w[(sl + 8) * S2STRIDE + g] = a1.x;
        S2w[(sl + 9) * S2STRIDE + g] = a1.y;
        S2w[(sl + 8) * S2STRIDE + g + 8] = a1.z;
        S2w[(sl + 9) * S2STRIDE + g + 8] = a1.w;
    }
    __syncwarp();

    for (int jt = 0; jt < 16; jt++) {
        const int j0 = jt << 6;

        // S2: new band tiles v in [j0+16, j0+80) -> 4 tile-pairs into ring
#pragma unroll
        for (int p = 0; p < 4; p++) {
            int v8 = ((j0 + 16) >> 3) + (p << 1);
            int pair = (v8 + nboff) >> 1;
            float4 a0 = make_float4(0.f, 0.f, 0.f, 0.f);
            float4 a1 = make_float4(0.f, 0.f, 0.f, 0.f);
#pragma unroll
            for (int kt = 0; kt < 4; kt++) {
                uint4 bb = *(const uint4*)(g_relp + (((size_t)kt * 136 + pair) << 7) + (lane << 2));
                mma16(a0, qf[kt], make_uint2(bb.x, bb.y));
                mma16(a1, qf[kt], make_uint2(bb.z, bb.w));
            }
            int sl = ((j0 + 16 + (p << 4)) & 127) + (tig << 1);
            S2w[sl * S2STRIDE + g] = a0.x;
            S2w[(sl + 1) * S2STRIDE + g] = a0.y;
            S2w[sl * S2STRIDE + g + 8] = a0.z;
            S2w[(sl + 1) * S2STRIDE + g + 8] = a0.w;
            S2w[(sl + 8) * S2STRIDE + g] = a1.x;
            S2w[(sl + 9) * S2STRIDE + g] = a1.y;
            S2w[(sl + 8) * S2STRIDE + g + 8] = a1.z;
            S2w[(sl + 9) * S2STRIDE + g + 8] = a1.w;
        }
        __syncwarp();

        // S1 = Q @ K^T over 4 n8-tile pairs
        float4 s1[8] = {};
#pragma unroll
        for (int kt = 0; kt < 4; kt++) {
#pragma unroll
            for (int p = 0; p < 4; p++) {
                uint4 kk = *(const uint4*)(kpb +
                    (((size_t)(kt * 64 + (j0 >> 4) + p)) << 7) + (lane << 2));
                mma16(s1[2 * p], qf[kt], make_uint2(kk.x, kk.y));
                mma16(s1[2 * p + 1], qf[kt], make_uint2(kk.z, kk.w));
            }
        }

        // gather ring + mask + row max (warp-local)
        float m0 = -1e30f, m1 = -1e30f;
#pragma unroll
        for (int nt = 0; nt < 8; nt++) {
            int c = (nt << 3) + (tig << 1);
            int v0 = j0 + c - g + 15;
            int v1 = v0 - 8;
            s1[nt].x += S2w[(v0 & 127) * S2STRIDE + g];
            s1[nt].y += S2w[((v0 + 1) & 127) * S2STRIDE + g];
            s1[nt].z += S2w[(v1 & 127) * S2STRIDE + g + 8];
            s1[nt].w += S2w[((v1 + 1) & 127) * S2STRIDE + g + 8];
            if (j0 + c >= NL) { s1[nt].x = -1e30f; s1[nt].z = -1e30f; }
            if (j0 + c + 1 >= NL) { s1[nt].y = -1e30f; s1[nt].w = -1e30f; }
            m0 = fmaxf(m0, fmaxf(s1[nt].x, s1[nt].y));
            m1 = fmaxf(m1, fmaxf(s1[nt].z, s1[nt].w));
        }
        m0 = fmaxf(m0, __shfl_xor_sync(0xffffffffu, m0, 1));
        m0 = fmaxf(m0, __shfl_xor_sync(0xffffffffu, m0, 2));
        m1 = fmaxf(m1, __shfl_xor_sync(0xffffffffu, m1, 1));
        m1 = fmaxf(m1, __shfl_xor_sync(0xffffffffu, m1, 2));

        // prefetch kt=0 V fragments — latency hides under the exp work below
        uint4 vv0[4];
#pragma unroll
        for (int p = 0; p < 4; p++)
            vv0[p] = *(const uint4*)(vpb + (((size_t)((j0 >> 4) << 2)) << 7) +
                                     (p << 7) + (lane << 2));

        float mn0 = fmaxf(rm0, m0), mn1 = fmaxf(rm1, m1);
        float a0 = ex2f(rm0 - mn0), a1 = ex2f(rm1 - mn1);
        rm0 = mn0; rm1 = mn1;

        // exp in f16x2 (half the MUFU ops, result IS the P fragment word)
        unsigned plo[8], phi[8];
#pragma unroll
        for (int nt = 0; nt < 8; nt++) {
            plo[nt] = hexp2p(s1[nt].x - mn0, s1[nt].y - mn0);
            phi[nt] = hexp2p(s1[nt].z - mn1, s1[nt].w - mn1);
        }

        // O rescale, then O += P @ V (f16), row sums via ones-mma
#pragma unroll
        for (int dnt = 0; dnt < 8; dnt++) {
            O[dnt].x *= a0; O[dnt].y *= a0;
            O[dnt].z *= a1; O[dnt].w *= a1;
        }
        float4 Ol = make_float4(0.f, 0.f, 0.f, 0.f);
        {
            uint4 pa = make_uint4(plo[0], phi[0], plo[1], phi[1]);
#pragma unroll
            for (int p = 0; p < 4; p++) {
                mma16h(O[2 * p], pa, make_uint2(vv0[p].x, vv0[p].y));
                mma16h(O[2 * p + 1], pa, make_uint2(vv0[p].z, vv0[p].w));
            }
            mma16h(Ol, pa, bones);
        }
#pragma unroll
        for (int kt = 1; kt < 4; kt++) {
            uint4 pa = make_uint4(plo[2 * kt], phi[2 * kt], plo[2 * kt + 1], phi[2 * kt + 1]);
            const unsigned* vb2 = vpb + (((size_t)(((j0 >> 4) + kt) << 2)) << 7) + (lane << 2);
#pragma unroll
            for (int p = 0; p < 4; p++) {
                uint4 vv = *(const uint4*)(vb2 + (p << 7));
                mma16h(O[2 * p], pa, make_uint2(vv.x, vv.y));
                mma16h(O[2 * p + 1], pa, make_uint2(vv.z, vv.w));
            }
            mma16h(Ol, pa, bones);
        }
        // broadcast col-0 sums (held by tig==0 lane of each row group)
        float lsum0 = __shfl_sync(0xffffffffu, Ol.x, lane & ~3);
        float lsum1 = __shfl_sync(0xffffffffu, Ol.z, lane & ~3);
        rl0 = rl0 * a0 + lsum0;
        rl1 = rl1 * a1 + lsum1;
        __syncwarp();
    }

    // normalize + write ctx as A-perm bf16
    float inv0 = 1.f / rl0, inv1 = 1.f / rl1;
    int r0g = i0 + (w << 4) + g, r1g = r0g + 8;
#pragma unroll
    for (int dnt = 0; dnt < 8; dnt++) {
        int col = (h << 6) + (dnt << 3) + (tig << 1);
        if (r0g < NL)
            g_ctxp[a_off16(bq * NL + r0g, col, 32)] = bf2(O[dnt].x * inv0, O[dnt].y * inv0);
        if (r1g < NL)
            g_ctxp[a_off16(bq * NL + r1g, col, 32)] = bf2(O[dnt].z * inv1, O[dnt].w * inv1);
    }
}

// ---------------- launch ------------------------------------------------------
extern "C" void kernel_launch(void* const* d_in, const int* in_sizes, int n_in,
                              void* d_out, int out_size) {
    const float* x     = (const float*)d_in[0];
    const float* Wq    = (const float*)d_in[1];
    const float* bq    = (const float*)d_in[2];
    const float* Wk    = (const float*)d_in[3];
    const float* bk    = (const float*)d_in[4];
    const float* Wv    = (const float*)d_in[5];
    const float* bv    = (const float*)d_in[6];
    const float* Wo    = (const float*)d_in[7];
    const float* bo    = (const float*)d_in[8];
    const float* rel   = (const float*)d_in[9];
    const float* gamma = (const float*)d_in[10];
    const float* beta  = (const float*)d_in[11];
    float* out = (float*)d_out;

    prep_kernel<<<1644, 256>>>(Wq, Wk, Wv, Wo, rel, x, gamma, beta);
    gemm2_kernel<<<dim3(8, 125, 3), 128>>>(bq, bk, bv, nullptr, nullptr, 0);  // QKV
    attn_kernel<<<dim3(16, NBH), 128>>>();
    gemm2_kernel<<<dim3(8, 125, 1), 128>>>(bo, nullptr, nullptr, x, out, 1);  // out-proj
}